// round 2
// baseline (speedup 1.0000x reference)
#include <cuda_runtime.h>

// ---------------------------------------------------------------------------
// AttentionOverride: GPT-2 attention block, fp32.
//   qkv = x @ w_attn + b_attn ; split q,k,v ; heads of 64
//   present[0]=K [B,H,S,64], present[1]=V [B,H,S,64]
//   w = softmax(scale*QK^T with -10000 on strict upper triangle)
//   w = where(mask, override, w)   (broadcast over batch)
//   a = merge_heads(w @ V) @ w_proj + b_proj
// Output layout: [ a (4M floats) | presentK (4M) | presentV (4M) ]
// ---------------------------------------------------------------------------

namespace {
constexpr int kB  = 4;
constexpr int kS  = 1024;
constexpr int kD  = 1024;
constexpr int kH  = 16;
constexpr int kHD = 64;
constexpr int kM  = kB * kS;  // 4096 rows

constexpr int kQT = 32;   // q rows per attention CTA
constexpr int kKC = 128;  // k chunk

constexpr int SST_STRIDE = 33;  // scores transposed [k][q]
constexpr int SQT_STRIDE = 36;  // Q transposed [d][q]
constexpr int SKV_STRIDE = 68;  // K/V natural [row][d]
constexpr int SMEM_FLOATS = kS * SST_STRIDE + kHD * SQT_STRIDE + kKC * SKV_STRIDE;
constexpr int SMEM_BYTES  = SMEM_FLOATS * 4;  // 179200 B
}  // namespace

__device__ float g_q[(size_t)kB * kH * kS * kHD];  // Q in [B,H,S,64]
__device__ float g_a[(size_t)kM * kD];             // merged attn out [B*S, D]
__device__ int   g_mask_kind;                      // 0=uint8, 1=int32, 2=float32

// ---------------------------------------------------------------------------
// Detect the storage type of the bool mask buffer.
//   int32:   every 32-bit word is 0 or 1
//   float32: every word is 0 or 0x3F800000
//   uint8:   words contain packed 0x00/0x01 bytes (some word >1, and packed
//            bytes can never form 0x3F800000)
// ---------------------------------------------------------------------------
__global__ void detect_mask_kind_kernel(const unsigned int* __restrict__ m) {
    __shared__ int any_gt1, any_not_f32;
    if (threadIdx.x == 0) { any_gt1 = 0; any_not_f32 = 0; }
    __syncthreads();
    int gt1 = 0, nf32 = 0;
    for (int i = threadIdx.x; i < 16384; i += 256) {
        unsigned int w = m[i];
        if (w > 1u) gt1 = 1;
        if (w != 0u && w != 0x3F800000u) nf32 = 1;
    }
    if (gt1)  atomicOr(&any_gt1, 1);
    if (nf32) atomicOr(&any_not_f32, 1);
    __syncthreads();
    if (threadIdx.x == 0)
        g_mask_kind = (!any_gt1) ? 1 : ((!any_not_f32) ? 2 : 0);
}

__device__ __forceinline__ bool mask_at(const void* __restrict__ mask,
                                        size_t idx, int kind) {
    if (kind == 1) return ((const int*)mask)[idx] != 0;
    if (kind == 2) return ((const float*)mask)[idx] != 0.0f;
    return ((const unsigned char*)mask)[idx] != 0;
}

// ---------------------------------------------------------------------------
// SGEMM: C[M,N] = A[M,K] @ W[K,N] + bias[N]
// 128x128 tile, BK=16, 256 threads, 8x8 per thread.
// mode 0: plain row-major store to C.
// mode 1: QKV split-scatter (q -> g_q, k -> kout(present0), v -> vout(present1))
// ---------------------------------------------------------------------------
__global__ __launch_bounds__(256, 2) void sgemm_kernel(
    const float* __restrict__ A, const float* __restrict__ W,
    const float* __restrict__ bias, float* __restrict__ C,
    int M, int N, int K, int mode,
    float* __restrict__ kout, float* __restrict__ vout)
{
    __shared__ float As[16][132];  // transposed: As[k][m], padded
    __shared__ float Bs[16][128];

    const int tid = threadIdx.x;
    const int m0 = blockIdx.y * 128;
    const int n0 = blockIdx.x * 128;
    const int tm0 = (tid / 16) * 8;
    const int tn0 = (tid % 16) * 8;

    const int arow = tid >> 2;         // 0..63
    const int acol = (tid & 3) << 2;   // 0,4,8,12
    const int brow = tid >> 5;         // 0..7
    const int bcol = (tid & 31) << 2;  // 0..124

    float acc[8][8] = {};

    for (int kk = 0; kk < K; kk += 16) {
        float4 a0 = *(const float4*)&A[(size_t)(m0 + arow) * K + kk + acol];
        float4 a1 = *(const float4*)&A[(size_t)(m0 + arow + 64) * K + kk + acol];
        As[acol + 0][arow] = a0.x;
        As[acol + 1][arow] = a0.y;
        As[acol + 2][arow] = a0.z;
        As[acol + 3][arow] = a0.w;
        As[acol + 0][arow + 64] = a1.x;
        As[acol + 1][arow + 64] = a1.y;
        As[acol + 2][arow + 64] = a1.z;
        As[acol + 3][arow + 64] = a1.w;
        *(float4*)&Bs[brow][bcol] =
            *(const float4*)&W[(size_t)(kk + brow) * N + n0 + bcol];
        *(float4*)&Bs[brow + 8][bcol] =
            *(const float4*)&W[(size_t)(kk + brow + 8) * N + n0 + bcol];
        __syncthreads();

#pragma unroll
        for (int k = 0; k < 16; ++k) {
            float4 fa0 = *(const float4*)&As[k][tm0];
            float4 fa1 = *(const float4*)&As[k][tm0 + 4];
            float4 fb0 = *(const float4*)&Bs[k][tn0];
            float4 fb1 = *(const float4*)&Bs[k][tn0 + 4];
            float rm[8] = {fa0.x, fa0.y, fa0.z, fa0.w, fa1.x, fa1.y, fa1.z, fa1.w};
            float rn[8] = {fb0.x, fb0.y, fb0.z, fb0.w, fb1.x, fb1.y, fb1.z, fb1.w};
#pragma unroll
            for (int i = 0; i < 8; ++i)
#pragma unroll
                for (int j = 0; j < 8; ++j)
                    acc[i][j] = fmaf(rm[i], rn[j], acc[i][j]);
        }
        __syncthreads();
    }

    if (mode == 0) {
#pragma unroll
        for (int i = 0; i < 8; ++i) {
            int m = m0 + tm0 + i;
#pragma unroll
            for (int j4 = 0; j4 < 8; j4 += 4) {
                int n = n0 + tn0 + j4;
                float4 o;
                o.x = acc[i][j4 + 0] + bias[n + 0];
                o.y = acc[i][j4 + 1] + bias[n + 1];
                o.z = acc[i][j4 + 2] + bias[n + 2];
                o.w = acc[i][j4 + 3] + bias[n + 3];
                *(float4*)&C[(size_t)m * N + n] = o;
            }
        }
    } else {
#pragma unroll
        for (int i = 0; i < 8; ++i) {
            int m = m0 + tm0 + i;
            int b = m >> 10;
            int s = m & 1023;
#pragma unroll
            for (int j = 0; j < 8; ++j) {
                int n = n0 + tn0 + j;
                float v = acc[i][j] + bias[n];
                int sec = n >> 10;       // 0=q 1=k 2=v
                int e = n & 1023;
                int h = e >> 6;
                int d = e & 63;
                int idx = (((b * kH + h) * kS) + s) * kHD + d;
                float* dst = (sec == 0) ? g_q : ((sec == 1) ? kout : vout);
                dst[idx] = v;
            }
        }
    }
}

// ---------------------------------------------------------------------------
// Fused attention: one CTA per (b, h, 32 q-rows). Scores kept in SMEM
// transposed [k][q] (stride 33, conflict-free column softmax).
// ---------------------------------------------------------------------------
__global__ __launch_bounds__(256) void attn_kernel(
    const float* __restrict__ Kp, const float* __restrict__ Vp,
    const float* __restrict__ ov, const void* __restrict__ mask,
    float* __restrict__ out)
{
    extern __shared__ float sm[];
    float* sST = sm;                              // [1024][33]
    float* sQT = sm + kS * SST_STRIDE;            // [64][36]
    float* sKV = sQT + kHD * SQT_STRIDE;          // [128][68]

    const int tid = threadIdx.x;
    const int b = blockIdx.z;
    const int h = blockIdx.y;
    const int q0 = blockIdx.x * kQT;
    const int mkind = g_mask_kind;

    const float* Qb = g_q + ((size_t)(b * kH + h) * kS + q0) * kHD;
    const float* Kb = Kp + (size_t)(b * kH + h) * kS * kHD;
    const float* Vb = Vp + (size_t)(b * kH + h) * kS * kHD;

    // ---- Load Q tile transposed: sQT[d][q] ----
#pragma unroll
    for (int it = 0; it < 2; ++it) {
        int t = tid + it * 256;       // float4 index 0..511
        int r = t >> 4;               // q row 0..31
        int d4 = (t & 15) << 2;       // 0..60
        float4 qv = *(const float4*)&Qb[r * kHD + d4];
        sQT[(d4 + 0) * SQT_STRIDE + r] = qv.x;
        sQT[(d4 + 1) * SQT_STRIDE + r] = qv.y;
        sQT[(d4 + 2) * SQT_STRIDE + r] = qv.z;
        sQT[(d4 + 3) * SQT_STRIDE + r] = qv.w;
    }
    __syncthreads();

    // ---- Scores: S^T[k][q] = scale * K[k,:] . Q[q,:], causal bias ----
    const int kr0 = (tid >> 3) << 2;  // k rows within chunk: 0..124
    const int qc0 = (tid & 7) << 2;   // q cols: 0..28
    const float scale = 0.125f;       // 1/sqrt(64)

    for (int kc = 0; kc < kS / kKC; ++kc) {
#pragma unroll
        for (int it = 0; it < 8; ++it) {
            int t = tid + it * 256;   // float4 index 0..2047
            int j = t >> 4;           // chunk row 0..127
            int d4 = (t & 15) << 2;
            *(float4*)&sKV[j * SKV_STRIDE + d4] =
                *(const float4*)&Kb[(size_t)(kc * kKC + j) * kHD + d4];
        }
        __syncthreads();

        float acc[4][4] = {};
#pragma unroll 16
        for (int d = 0; d < kHD; ++d) {
            float kv[4];
#pragma unroll
            for (int i = 0; i < 4; ++i) kv[i] = sKV[(kr0 + i) * SKV_STRIDE + d];
            float4 qv4 = *(const float4*)&sQT[d * SQT_STRIDE + qc0];
            float qa[4] = {qv4.x, qv4.y, qv4.z, qv4.w};
#pragma unroll
            for (int i = 0; i < 4; ++i)
#pragma unroll
                for (int j = 0; j < 4; ++j)
                    acc[i][j] = fmaf(kv[i], qa[j], acc[i][j]);
        }

#pragma unroll
        for (int i = 0; i < 4; ++i) {
            int kg = kc * kKC + kr0 + i;
#pragma unroll
            for (int j = 0; j < 4; ++j) {
                int qg = q0 + qc0 + j;
                sST[kg * SST_STRIDE + qc0 + j] =
                    (kg <= qg) ? acc[i][j] * scale : -10000.0f;
            }
        }
        __syncthreads();
    }

    // ---- Softmax over k (columns of sST) + override; warp handles 4 q rows ----
    {
        const int warp = tid >> 5;
        const int lane = tid & 31;
#pragma unroll
        for (int rr = 0; rr < 4; ++rr) {
            int r = warp * 4 + rr;
            float mx = -1e30f;
#pragma unroll
            for (int t = 0; t < 32; ++t)
                mx = fmaxf(mx, sST[(lane + t * 32) * SST_STRIDE + r]);
#pragma unroll
            for (int o = 16; o; o >>= 1)
                mx = fmaxf(mx, __shfl_xor_sync(0xffffffffu, mx, o));
            float sum = 0.f;
#pragma unroll
            for (int t = 0; t < 32; ++t) {
                int k = lane + t * 32;
                float e = __expf(sST[k * SST_STRIDE + r] - mx);
                sST[k * SST_STRIDE + r] = e;
                sum += e;
            }
#pragma unroll
            for (int o = 16; o; o >>= 1)
                sum += __shfl_xor_sync(0xffffffffu, sum, o);
            float inv = 1.0f / sum;
            size_t base = ((size_t)h * kS + (size_t)(q0 + r)) * kS;
#pragma unroll
            for (int t = 0; t < 32; ++t) {
                int k = lane + t * 32;
                float p = sST[k * SST_STRIDE + r] * inv;
                if (mask_at(mask, base + k, mkind)) p = ov[base + k];
                sST[k * SST_STRIDE + r] = p;
            }
        }
    }
    __syncthreads();

    // ---- AV: O[32][64] = P[32][1024] @ V[1024][64] ----
    const int r2 = (tid >> 4) << 1;   // q rows r2, r2+1
    const int c4 = (tid & 15) << 2;   // d cols c4..c4+3
    float o0[4] = {}, o1[4] = {};
    for (int kc = 0; kc < kS / kKC; ++kc) {
#pragma unroll
        for (int it = 0; it < 8; ++it) {
            int t = tid + it * 256;
            int j = t >> 4;
            int d4 = (t & 15) << 2;
            *(float4*)&sKV[j * SKV_STRIDE + d4] =
                *(const float4*)&Vb[(size_t)(kc * kKC + j) * kHD + d4];
        }
        __syncthreads();
#pragma unroll 8
        for (int k = 0; k < kKC; ++k) {
            int kg = kc * kKC + k;
            float p0 = sST[kg * SST_STRIDE + r2];
            float p1 = sST[kg * SST_STRIDE + r2 + 1];
            float4 v = *(const float4*)&sKV[k * SKV_STRIDE + c4];
            o0[0] = fmaf(p0, v.x, o0[0]);
            o0[1] = fmaf(p0, v.y, o0[1]);
            o0[2] = fmaf(p0, v.z, o0[2]);
            o0[3] = fmaf(p0, v.w, o0[3]);
            o1[0] = fmaf(p1, v.x, o1[0]);
            o1[1] = fmaf(p1, v.y, o1[1]);
            o1[2] = fmaf(p1, v.z, o1[2]);
            o1[3] = fmaf(p1, v.w, o1[3]);
        }
        __syncthreads();
    }

    // merged-head layout: out[(b*S + q)*D + h*64 + d]
    float* ob = out + ((size_t)(b * kS + q0 + r2) * kD) + h * kHD + c4;
    *(float4*)ob = make_float4(o0[0], o0[1], o0[2], o0[3]);
    *(float4*)(ob + kD) = make_float4(o1[0], o1[1], o1[2], o1[3]);
}

// ---------------------------------------------------------------------------
extern "C" void kernel_launch(void* const* d_in, const int* in_sizes, int n_in,
                              void* d_out, int out_size)
{
    const float* x       = (const float*)d_in[0];
    const float* w_attn  = (const float*)d_in[1];
    const float* b_attn  = (const float*)d_in[2];
    const float* w_proj  = (const float*)d_in[3];
    const float* b_proj  = (const float*)d_in[4];
    const float* ov      = (const float*)d_in[5];
    const void*  msk     = (const void*)d_in[6];

    float* out = (float*)d_out;
    float* presentK = out + (size_t)kM * kD;                      // 4M floats in
    float* presentV = presentK + (size_t)kB * kH * kS * kHD;      // +4M

    float* aptr = nullptr;
    cudaGetSymbolAddress((void**)&aptr, g_a);

    cudaFuncSetAttribute(attn_kernel,
                         cudaFuncAttributeMaxDynamicSharedMemorySize, SMEM_BYTES);

    dim3 blk(256);
    // 0) classify mask storage type
    detect_mask_kind_kernel<<<1, 256>>>((const unsigned int*)msk);
    // 1) QKV GEMM with split-scatter epilogue
    sgemm_kernel<<<dim3(3 * kD / 128, kM / 128), blk>>>(
        x, w_attn, b_attn, nullptr, kM, 3 * kD, kD, 1, presentK, presentV);
    // 2) fused attention -> g_a (merged heads)
    attn_kernel<<<dim3(kS / kQT, kH, kB), blk, SMEM_BYTES>>>(
        presentK, presentV, ov, msk, aptr);
    // 3) output projection -> out[0:4M]
    sgemm_kernel<<<dim3(kD / 128, kM / 128), blk>>>(
        aptr, w_proj, b_proj, out, kM, kD, kD, 0, nullptr, nullptr);
}

// round 4
// speedup vs baseline: 1.3402x; 1.3402x over previous
#include <cuda_runtime.h>
#include <cuda_bf16.h>
#include <cstdint>

// ---------------------------------------------------------------------------
// AttentionOverride, round 4: bf16 hi/lo split GEMMs on mma.sync (HMMA),
// fp32 fused attention. tcgen05 is unavailable (harness targets compute_103
// virtual arch, which lacks the sm_103a feature set).
// Output layout: [ a (4M floats) | presentK (4M) | presentV (4M) ]
// ---------------------------------------------------------------------------

namespace {
constexpr int kB  = 4;
constexpr int kS  = 1024;
constexpr int kD  = 1024;
constexpr int kH  = 16;
constexpr int kHD = 64;
constexpr int kM  = kB * kS;  // 4096

constexpr int kQT = 32;
constexpr int kKC = 128;
constexpr int SST_STRIDE = 33;
constexpr int SQT_STRIDE = 36;
constexpr int SKV_STRIDE = 68;
constexpr int ATT_SMEM_FLOATS = kS * SST_STRIDE + kHD * SQT_STRIDE + kKC * SKV_STRIDE;
constexpr int ATT_SMEM_BYTES  = ATT_SMEM_FLOATS * 4;  // 179200

constexpr int kSTR = 40;  // smem row stride in bf16 (bank-stagger 20 -> conflict-free frags)
}  // namespace

// scratch (device globals; no allocation allowed)
__device__ float g_q[(size_t)kB * kH * kS * kHD];
__device__ float g_a[(size_t)kM * kD];
__device__ int   g_mask_kind;
__device__ __nv_bfloat16 g_xh[(size_t)kM * kD];
__device__ __nv_bfloat16 g_xl[(size_t)kM * kD];
__device__ __nv_bfloat16 g_ah[(size_t)kM * kD];
__device__ __nv_bfloat16 g_al[(size_t)kM * kD];
__device__ __nv_bfloat16 g_wth[(size_t)3 * kD * kD];  // w_attn^T [3072,1024]
__device__ __nv_bfloat16 g_wtl[(size_t)3 * kD * kD];
__device__ __nv_bfloat16 g_pth[(size_t)kD * kD];      // w_proj^T [1024,1024]
__device__ __nv_bfloat16 g_ptl[(size_t)kD * kD];

// ---------------------------------------------------------------------------
// m16n8k16 bf16 MMA (sm_80+ plain PTX; assembles under compute_103)
// ---------------------------------------------------------------------------
__device__ __forceinline__ void mma16816(float* c, const uint32_t* a,
                                         uint32_t b0, uint32_t b1) {
    asm volatile(
        "mma.sync.aligned.m16n8k16.row.col.f32.bf16.bf16.f32 "
        "{%0,%1,%2,%3}, {%4,%5,%6,%7}, {%8,%9}, {%0,%1,%2,%3};"
        : "+f"(c[0]), "+f"(c[1]), "+f"(c[2]), "+f"(c[3])
        : "r"(a[0]), "r"(a[1]), "r"(a[2]), "r"(a[3]), "r"(b0), "r"(b1));
}

// ---------------------------------------------------------------------------
// Prepass kernels
// ---------------------------------------------------------------------------
__device__ __forceinline__ void split2(float x, __nv_bfloat16& h, __nv_bfloat16& l) {
    h = __float2bfloat16(x);
    l = __float2bfloat16(x - __bfloat162float(h));
}

__global__ void split_kernel(const float* __restrict__ X,
                             __nv_bfloat16* __restrict__ H,
                             __nv_bfloat16* __restrict__ L, int n) {
    int i = blockIdx.x * 256 + threadIdx.x;
    if (i < n) split2(X[i], H[i], L[i]);
}

// W[K,N] fp32 -> Th/Tl [N,K] bf16
__global__ void transpose_split_kernel(const float* __restrict__ W,
                                       __nv_bfloat16* __restrict__ Th,
                                       __nv_bfloat16* __restrict__ Tl,
                                       int K, int N) {
    __shared__ float t[32][33];
    int n0 = blockIdx.x * 32, k0 = blockIdx.y * 32;
    int tx = threadIdx.x, ty = threadIdx.y;  // (32,8)
#pragma unroll
    for (int j = 0; j < 4; ++j)
        t[ty + j * 8][tx] = W[(size_t)(k0 + ty + j * 8) * N + n0 + tx];
    __syncthreads();
#pragma unroll
    for (int j = 0; j < 4; ++j) {
        float v = t[tx][ty + j * 8];
        __nv_bfloat16 h, l;
        split2(v, h, l);
        size_t o = (size_t)(n0 + ty + j * 8) * K + k0 + tx;
        Th[o] = h;
        Tl[o] = l;
    }
}

__global__ void detect_mask_kind_kernel(const unsigned int* __restrict__ m) {
    __shared__ int any_gt1, any_not_f32;
    if (threadIdx.x == 0) { any_gt1 = 0; any_not_f32 = 0; }
    __syncthreads();
    int gt1 = 0, nf32 = 0;
    for (int i = threadIdx.x; i < 16384; i += 256) {
        unsigned int w = m[i];
        if (w > 1u) gt1 = 1;
        if (w != 0u && w != 0x3F800000u) nf32 = 1;
    }
    if (gt1)  atomicOr(&any_gt1, 1);
    if (nf32) atomicOr(&any_not_f32, 1);
    __syncthreads();
    if (threadIdx.x == 0)
        g_mask_kind = (!any_gt1) ? 1 : ((!any_not_f32) ? 2 : 0);
}

__device__ __forceinline__ bool mask_at(const void* __restrict__ mask,
                                        size_t idx, int kind) {
    if (kind == 1) return ((const int*)mask)[idx] != 0;
    if (kind == 2) return ((const float*)mask)[idx] != 0.0f;
    return ((const unsigned char*)mask)[idx] != 0;
}

// ---------------------------------------------------------------------------
// HMMA GEMM: C[M,N] = Ahl[M,K] @ Bhl[N,K]^T + bias
// 128x128 CTA tile, 8 warps (4Mx2N), warp tile 32x64, BK=32.
// hi/lo split: acc += Ah*Bh + Al*Bh + Ah*Bl.
// mode 0: row-major C. mode 1: QKV scatter (q->g_q, k->kout, v->vout).
// ---------------------------------------------------------------------------
__global__ __launch_bounds__(256, 2) void mma_gemm_kernel(
    const __nv_bfloat16* __restrict__ Ah, const __nv_bfloat16* __restrict__ Al,
    const __nv_bfloat16* __restrict__ Bh, const __nv_bfloat16* __restrict__ Bl,
    const float* __restrict__ bias, float* __restrict__ C,
    int M, int N, int K, int mode,
    float* __restrict__ kout, float* __restrict__ vout)
{
    __shared__ __nv_bfloat16 sAh[128 * kSTR], sAl[128 * kSTR];
    __shared__ __nv_bfloat16 sBh[128 * kSTR], sBl[128 * kSTR];

    const int tid = threadIdx.x;
    const int lane = tid & 31;
    const int wid = tid >> 5;
    const int wm = (wid & 3) * 32;   // warp M offset in tile
    const int wn = (wid >> 2) * 64;  // warp N offset in tile
    const int m0 = blockIdx.y * 128;
    const int n0 = blockIdx.x * 128;

    const int gID = lane >> 2;        // group id 0..7
    const int tig2 = (lane & 3) * 2;  // 0,2,4,6

    float acc[2][8][4] = {};

    for (int c = 0; c < K / 32; ++c) {
        // load 4 tiles of 128 rows x 32 bf16 (64B/row, 4 x float4)
#pragma unroll
        for (int j = 0; j < 2; ++j) {
            int unit = tid + j * 256;  // 0..511
            int rr = unit >> 2;        // row 0..127
            int uu = unit & 3;         // float4 unit in row
            size_t ga = (size_t)(m0 + rr) * K + c * 32 + uu * 8;
            size_t gb = (size_t)(n0 + rr) * K + c * 32 + uu * 8;
            int so = rr * kSTR + uu * 8;
            *(float4*)&sAh[so] = *(const float4*)&Ah[ga];
            *(float4*)&sAl[so] = *(const float4*)&Al[ga];
            *(float4*)&sBh[so] = *(const float4*)&Bh[gb];
            *(float4*)&sBl[so] = *(const float4*)&Bl[gb];
        }
        __syncthreads();

#pragma unroll
        for (int ks = 0; ks < 2; ++ks) {
            const int k0 = ks * 16;
            uint32_t ah[2][4], al[2][4];
#pragma unroll
            for (int mi = 0; mi < 2; ++mi) {
                int base = (wm + mi * 16 + gID) * kSTR + k0 + tig2;
                ah[mi][0] = *(const uint32_t*)&sAh[base];
                ah[mi][1] = *(const uint32_t*)&sAh[base + 8 * kSTR];
                ah[mi][2] = *(const uint32_t*)&sAh[base + 8];
                ah[mi][3] = *(const uint32_t*)&sAh[base + 8 * kSTR + 8];
                al[mi][0] = *(const uint32_t*)&sAl[base];
                al[mi][1] = *(const uint32_t*)&sAl[base + 8 * kSTR];
                al[mi][2] = *(const uint32_t*)&sAl[base + 8];
                al[mi][3] = *(const uint32_t*)&sAl[base + 8 * kSTR + 8];
            }
#pragma unroll
            for (int nt = 0; nt < 8; ++nt) {
                int nb = (wn + nt * 8 + gID) * kSTR + k0 + tig2;
                uint32_t bh0 = *(const uint32_t*)&sBh[nb];
                uint32_t bh1 = *(const uint32_t*)&sBh[nb + 8];
                mma16816(acc[0][nt], ah[0], bh0, bh1);
                mma16816(acc[1][nt], ah[1], bh0, bh1);
                mma16816(acc[0][nt], al[0], bh0, bh1);
                mma16816(acc[1][nt], al[1], bh0, bh1);
                uint32_t bl0 = *(const uint32_t*)&sBl[nb];
                uint32_t bl1 = *(const uint32_t*)&sBl[nb + 8];
                mma16816(acc[0][nt], ah[0], bl0, bl1);
                mma16816(acc[1][nt], ah[1], bl0, bl1);
            }
        }
        __syncthreads();
    }

    // ---- epilogue ----
#pragma unroll
    for (int mi = 0; mi < 2; ++mi) {
#pragma unroll
        for (int nt = 0; nt < 8; ++nt) {
            int m = m0 + wm + mi * 16 + gID;
            int n = n0 + wn + nt * 8 + tig2;
            float b0 = bias[n], b1 = bias[n + 1];
            float v0 = acc[mi][nt][0] + b0;
            float v1 = acc[mi][nt][1] + b1;
            float v2 = acc[mi][nt][2] + b0;  // row m+8
            float v3 = acc[mi][nt][3] + b1;
            if (mode == 0) {
                *(float2*)&C[(size_t)m * N + n] = make_float2(v0, v1);
                *(float2*)&C[(size_t)(m + 8) * N + n] = make_float2(v2, v3);
            } else {
                int sec = n >> 10;           // 0=q 1=k 2=v
                int e = n & 1023;
                int h = e >> 6;
                int d = e & 63;              // even
                float* dst = (sec == 0) ? g_q : ((sec == 1) ? kout : vout);
#pragma unroll
                for (int rr = 0; rr < 2; ++rr) {
                    int mm = m + rr * 8;
                    int b = mm >> 10;
                    int s = mm & 1023;
                    size_t idx = (((size_t)(b * kH + h) * kS) + s) * kHD + d;
                    *(float2*)&dst[idx] = rr ? make_float2(v2, v3)
                                             : make_float2(v0, v1);
                }
            }
        }
    }
}

// ---------------------------------------------------------------------------
// Fused attention (unchanged, proven): one CTA per (b, h, 32 q-rows).
// ---------------------------------------------------------------------------
__global__ __launch_bounds__(256) void attn_kernel(
    const float* __restrict__ Kp, const float* __restrict__ Vp,
    const float* __restrict__ ov, const void* __restrict__ mask,
    float* __restrict__ out)
{
    extern __shared__ float sm[];
    float* sST = sm;
    float* sQT = sm + kS * SST_STRIDE;
    float* sKV = sQT + kHD * SQT_STRIDE;

    const int tid = threadIdx.x;
    const int b = blockIdx.z;
    const int h = blockIdx.y;
    const int q0 = blockIdx.x * kQT;
    const int mkind = g_mask_kind;

    const float* Qb = g_q + ((size_t)(b * kH + h) * kS + q0) * kHD;
    const float* Kb = Kp + (size_t)(b * kH + h) * kS * kHD;
    const float* Vb = Vp + (size_t)(b * kH + h) * kS * kHD;

#pragma unroll
    for (int it = 0; it < 2; ++it) {
        int t = tid + it * 256;
        int r = t >> 4;
        int d4 = (t & 15) << 2;
        float4 qv = *(const float4*)&Qb[r * kHD + d4];
        sQT[(d4 + 0) * SQT_STRIDE + r] = qv.x;
        sQT[(d4 + 1) * SQT_STRIDE + r] = qv.y;
        sQT[(d4 + 2) * SQT_STRIDE + r] = qv.z;
        sQT[(d4 + 3) * SQT_STRIDE + r] = qv.w;
    }
    __syncthreads();

    const int kr0 = (tid >> 3) << 2;
    const int qc0 = (tid & 7) << 2;
    const float scale = 0.125f;

    for (int kc = 0; kc < kS / kKC; ++kc) {
#pragma unroll
        for (int it = 0; it < 8; ++it) {
            int t = tid + it * 256;
            int j = t >> 4;
            int d4 = (t & 15) << 2;
            *(float4*)&sKV[j * SKV_STRIDE + d4] =
                *(const float4*)&Kb[(size_t)(kc * kKC + j) * kHD + d4];
        }
        __syncthreads();

        float acc[4][4] = {};
#pragma unroll 16
        for (int d = 0; d < kHD; ++d) {
            float kv[4];
#pragma unroll
            for (int i = 0; i < 4; ++i) kv[i] = sKV[(kr0 + i) * SKV_STRIDE + d];
            float4 qv4 = *(const float4*)&sQT[d * SQT_STRIDE + qc0];
            float qa[4] = {qv4.x, qv4.y, qv4.z, qv4.w};
#pragma unroll
            for (int i = 0; i < 4; ++i)
#pragma unroll
                for (int j = 0; j < 4; ++j)
                    acc[i][j] = fmaf(kv[i], qa[j], acc[i][j]);
        }

#pragma unroll
        for (int i = 0; i < 4; ++i) {
            int kg = kc * kKC + kr0 + i;
#pragma unroll
            for (int j = 0; j < 4; ++j) {
                int qg = q0 + qc0 + j;
                sST[kg * SST_STRIDE + qc0 + j] =
                    (kg <= qg) ? acc[i][j] * scale : -10000.0f;
            }
        }
        __syncthreads();
    }

    {
        const int warp = tid >> 5;
        const int lane = tid & 31;
#pragma unroll
        for (int rr = 0; rr < 4; ++rr) {
            int r = warp * 4 + rr;
            float mx = -1e30f;
#pragma unroll
            for (int t = 0; t < 32; ++t)
                mx = fmaxf(mx, sST[(lane + t * 32) * SST_STRIDE + r]);
#pragma unroll
            for (int o = 16; o; o >>= 1)
                mx = fmaxf(mx, __shfl_xor_sync(0xffffffffu, mx, o));
            float sum = 0.f;
#pragma unroll
            for (int t = 0; t < 32; ++t) {
                int k = lane + t * 32;
                float e = __expf(sST[k * SST_STRIDE + r] - mx);
                sST[k * SST_STRIDE + r] = e;
                sum += e;
            }
#pragma unroll
            for (int o = 16; o; o >>= 1)
                sum += __shfl_xor_sync(0xffffffffu, sum, o);
            float inv = 1.0f / sum;
            size_t base = ((size_t)h * kS + (size_t)(q0 + r)) * kS;
#pragma unroll
            for (int t = 0; t < 32; ++t) {
                int k = lane + t * 32;
                float p = sST[k * SST_STRIDE + r] * inv;
                if (mask_at(mask, base + k, mkind)) p = ov[base + k];
                sST[k * SST_STRIDE + r] = p;
            }
        }
    }
    __syncthreads();

    const int r2 = (tid >> 4) << 1;
    const int c4 = (tid & 15) << 2;
    float o0[4] = {}, o1[4] = {};
    for (int kc = 0; kc < kS / kKC; ++kc) {
#pragma unroll
        for (int it = 0; it < 8; ++it) {
            int t = tid + it * 256;
            int j = t >> 4;
            int d4 = (t & 15) << 2;
            *(float4*)&sKV[j * SKV_STRIDE + d4] =
                *(const float4*)&Vb[(size_t)(kc * kKC + j) * kHD + d4];
        }
        __syncthreads();
#pragma unroll 8
        for (int k = 0; k < kKC; ++k) {
            int kg = kc * kKC + k;
            float p0 = sST[kg * SST_STRIDE + r2];
            float p1 = sST[kg * SST_STRIDE + r2 + 1];
            float4 v = *(const float4*)&sKV[k * SKV_STRIDE + c4];
            o0[0] = fmaf(p0, v.x, o0[0]);
            o0[1] = fmaf(p0, v.y, o0[1]);
            o0[2] = fmaf(p0, v.z, o0[2]);
            o0[3] = fmaf(p0, v.w, o0[3]);
            o1[0] = fmaf(p1, v.x, o1[0]);
            o1[1] = fmaf(p1, v.y, o1[1]);
            o1[2] = fmaf(p1, v.z, o1[2]);
            o1[3] = fmaf(p1, v.w, o1[3]);
        }
        __syncthreads();
    }

    float* ob = out + ((size_t)(b * kS + q0 + r2) * kD) + h * kHD + c4;
    *(float4*)ob = make_float4(o0[0], o0[1], o0[2], o0[3]);
    *(float4*)(ob + kD) = make_float4(o1[0], o1[1], o1[2], o1[3]);
}

// ---------------------------------------------------------------------------
extern "C" void kernel_launch(void* const* d_in, const int* in_sizes, int n_in,
                              void* d_out, int out_size)
{
    const float* x       = (const float*)d_in[0];
    const float* w_attn  = (const float*)d_in[1];
    const float* b_attn  = (const float*)d_in[2];
    const float* w_proj  = (const float*)d_in[3];
    const float* b_proj  = (const float*)d_in[4];
    const float* ov      = (const float*)d_in[5];
    const void*  msk     = (const void*)d_in[6];

    float* out = (float*)d_out;
    float* presentK = out + (size_t)kM * kD;
    float* presentV = presentK + (size_t)kB * kH * kS * kHD;

    float *aptr = nullptr;
    __nv_bfloat16 *xh, *xl, *ah, *al, *wth, *wtl, *pth, *ptl;
    cudaGetSymbolAddress((void**)&aptr, g_a);
    cudaGetSymbolAddress((void**)&xh, g_xh);
    cudaGetSymbolAddress((void**)&xl, g_xl);
    cudaGetSymbolAddress((void**)&ah, g_ah);
    cudaGetSymbolAddress((void**)&al, g_al);
    cudaGetSymbolAddress((void**)&wth, g_wth);
    cudaGetSymbolAddress((void**)&wtl, g_wtl);
    cudaGetSymbolAddress((void**)&pth, g_pth);
    cudaGetSymbolAddress((void**)&ptl, g_ptl);

    cudaFuncSetAttribute(attn_kernel,
                         cudaFuncAttributeMaxDynamicSharedMemorySize, ATT_SMEM_BYTES);

    // 0) mask classification + operand prep
    detect_mask_kind_kernel<<<1, 256>>>((const unsigned int*)msk);
    split_kernel<<<kM * kD / 256, 256>>>(x, xh, xl, kM * kD);
    transpose_split_kernel<<<dim3(3 * kD / 32, kD / 32), dim3(32, 8)>>>(
        w_attn, wth, wtl, kD, 3 * kD);
    transpose_split_kernel<<<dim3(kD / 32, kD / 32), dim3(32, 8)>>>(
        w_proj, pth, ptl, kD, kD);

    // 1) QKV GEMM (HMMA) with split-scatter epilogue
    mma_gemm_kernel<<<dim3(3 * kD / 128, kM / 128), 256>>>(
        xh, xl, wth, wtl, b_attn, nullptr, kM, 3 * kD, kD, 1, presentK, presentV);

    // 2) fused attention -> g_a
    attn_kernel<<<dim3(kS / kQT, kH, kB), 256, ATT_SMEM_BYTES>>>(
        presentK, presentV, ov, msk, aptr);

    // 3) split g_a, then output projection (HMMA)
    split_kernel<<<kM * kD / 256, 256>>>(aptr, ah, al, kM * kD);
    mma_gemm_kernel<<<dim3(kD / 128, kM / 128), 256>>>(
        ah, al, pth, ptl, b_proj, out, kM, kD, kD, 0, nullptr, nullptr);
}